// round 12
// baseline (speedup 1.0000x reference)
#include <cuda_runtime.h>
#include <cuda_bf16.h>
#include <math.h>
#include <stdint.h>

// ---------------- problem dims ----------------
#define BB 2
#define SS 2048
#define DD 1024
#define HH 16
#define HDD 64
#define II 3752
#define MM (BB*SS)          // 4096
#define QKVN 3072
#define IPAD 3840
#define GUN (2*IPAD)        // 7680

// ---------------- scratch ----------------
__device__ __nv_bfloat16 g_h_hi[MM*DD],  g_h_lo[MM*DD];
__device__ __nv_bfloat16 g_qkv_hi[(size_t)MM*QKVN], g_qkv_lo[(size_t)MM*QKVN];
__device__ __nv_bfloat16 g_attn_hi[MM*DD], g_attn_lo[MM*DD];
__device__ float         g_res1[MM*DD];
__device__ __nv_bfloat16 g_h2_hi[MM*DD], g_h2_lo[MM*DD];
__device__ __nv_bfloat16 g_act_hi[(size_t)MM*IPAD], g_act_lo[(size_t)MM*IPAD];
__device__ __nv_bfloat16 g_wqkvT_hi[QKVN*DD], g_wqkvT_lo[QKVN*DD];
__device__ __nv_bfloat16 g_woT_hi[DD*DD],     g_woT_lo[DD*DD];
__device__ __nv_bfloat16 g_wguT_hi[GUN*DD],   g_wguT_lo[GUN*DD];
__device__ __nv_bfloat16 g_wdT_hi[DD*IPAD],   g_wdT_lo[DD*IPAD];
__device__ float         g_bqkv[QKVN];

// ---------------- helpers ----------------
__device__ __forceinline__ uint32_t smem_u32(const void* p){
    uint32_t r;
    asm("{ .reg .u64 t; cvta.to.shared.u64 t, %1; cvt.u32.u64 %0, t; }" : "=r"(r) : "l"(p));
    return r;
}
#define SWZ64(x)  ((x) ^ (((x) >> 3) & 0x30))
#define SWZ128(x) ((x) ^ (((x) >> 3) & 0x70))

__device__ __forceinline__ void ldsm_x4(uint32_t* r, uint32_t a){
    asm volatile("ldmatrix.sync.aligned.m8n8.x4.shared.b16 {%0,%1,%2,%3}, [%4];"
        : "=r"(r[0]), "=r"(r[1]), "=r"(r[2]), "=r"(r[3]) : "r"(a));
}
__device__ __forceinline__ void ldsm_x4_t(uint32_t* r, uint32_t a){
    asm volatile("ldmatrix.sync.aligned.m8n8.x4.trans.shared.b16 {%0,%1,%2,%3}, [%4];"
        : "=r"(r[0]), "=r"(r[1]), "=r"(r[2]), "=r"(r[3]) : "r"(a));
}
__device__ __forceinline__ void mma_bf16(float* c, const uint32_t* a, uint32_t b0, uint32_t b1){
    asm volatile("mma.sync.aligned.m16n8k16.row.col.f32.bf16.bf16.f32 "
        "{%0,%1,%2,%3}, {%4,%5,%6,%7}, {%8,%9}, {%0,%1,%2,%3};"
        : "+f"(c[0]), "+f"(c[1]), "+f"(c[2]), "+f"(c[3])
        : "r"(a[0]), "r"(a[1]), "r"(a[2]), "r"(a[3]), "r"(b0), "r"(b1));
}
__device__ __forceinline__ uint32_t pack_bf16(float lo_elem, float hi_elem){
    uint32_t r;
    asm("cvt.rn.bf16x2.f32 %0, %1, %2;" : "=r"(r) : "f"(hi_elem), "f"(lo_elem));
    return r;
}
#define CPA16(d, g) asm volatile("cp.async.cg.shared.global [%0], [%1], 16;\n" :: "r"(d), "l"(g))
#define CPA_COMMIT() asm volatile("cp.async.commit_group;\n" ::: "memory")

// ---------------- HMMA GEMM (R8-proven: 4 stages, 1 CTA/SM) ----------------
#define GBK 32
#define STAGES 4
#define TILEB (128*32*2)
#define STGB (4*TILEB)
#define GEMM_SMEM (STAGES*STGB)    // 131072

__global__ __launch_bounds__(256, 1)
void tc_gemm(const __nv_bfloat16* __restrict__ Ahi, const __nv_bfloat16* __restrict__ Alo,
             const __nv_bfloat16* __restrict__ Bhi, const __nv_bfloat16* __restrict__ Blo,
             const float* __restrict__ bias, const float* __restrict__ add,
             float* __restrict__ C, int K, int ldc,
             __nv_bfloat16* __restrict__ Ohi, __nv_bfloat16* __restrict__ Olo, int qscale_cols)
{
    extern __shared__ __align__(1024) char smem[];
    uint32_t sb = smem_u32(smem);
    int tid = threadIdx.x, wid = tid >> 5, lane = tid & 31;
    int m0 = blockIdx.y * 128, n0 = blockIdx.x * 128;
    int warp_m = wid & 3, warp_n = wid >> 2;

    const int KT = K / GBK;

    auto issue_loads = [&](int s, int kt){
        int k0 = kt * GBK;
        uint32_t stg = sb + s * STGB;
        #pragma unroll
        for (int t = 0; t < 4; t++) {
            const __nv_bfloat16* src = (t == 0 ? Ahi : t == 1 ? Alo : t == 2 ? Bhi : Blo);
            int rb = (t < 2 ? m0 : n0);
            #pragma unroll
            for (int i = 0; i < 2; i++) {
                int id = i * 256 + tid;
                int r = id >> 2, c = id & 3;
                const void* g = src + (size_t)(rb + r) * K + k0 + c * 8;
                uint32_t d = stg + t * TILEB + SWZ64((uint32_t)(r * 64 + c * 16));
                CPA16(d, g);
            }
        }
        CPA_COMMIT();
    };

    float acc[2][8][4];
    #pragma unroll
    for (int mt = 0; mt < 2; mt++)
        #pragma unroll
        for (int nt = 0; nt < 8; nt++)
            #pragma unroll
            for (int i = 0; i < 4; i++) acc[mt][nt][i] = 0.0f;

    issue_loads(0, 0);
    issue_loads(1, 1);
    issue_loads(2, 2);

    for (int kt = 0; kt < KT; kt++) {
        asm volatile("cp.async.wait_group 2;\n" ::: "memory");
        __syncthreads();
        if (kt + 3 < KT) issue_loads((kt + 3) % STAGES, kt + 3);

        uint32_t stg = sb + (kt % STAGES) * STGB;
        #pragma unroll
        for (int kk = 0; kk < 2; kk++) {
            uint32_t a_h[2][4], a_l[2][4];
            #pragma unroll
            for (int mt = 0; mt < 2; mt++) {
                int row = warp_m * 32 + mt * 16 + (lane & 15);
                uint32_t sw = SWZ64((uint32_t)(row * 64 + kk * 32 + (lane >> 4) * 16));
                ldsm_x4(a_h[mt], stg + sw);
                ldsm_x4(a_l[mt], stg + TILEB + sw);
            }
            uint32_t b_h[8][2], b_l[8][2];
            #pragma unroll
            for (int np = 0; np < 4; np++) {
                int nrow = warp_n * 64 + np * 16 + (lane & 7) + ((lane >> 4) << 3);
                uint32_t sw = SWZ64((uint32_t)(nrow * 64 + kk * 32 + ((lane >> 3) & 1) * 16));
                uint32_t t4[4];
                ldsm_x4(t4, stg + 2 * TILEB + sw);
                b_h[2*np][0] = t4[0]; b_h[2*np][1] = t4[1];
                b_h[2*np+1][0] = t4[2]; b_h[2*np+1][1] = t4[3];
                ldsm_x4(t4, stg + 3 * TILEB + sw);
                b_l[2*np][0] = t4[0]; b_l[2*np][1] = t4[1];
                b_l[2*np+1][0] = t4[2]; b_l[2*np+1][1] = t4[3];
            }
            #pragma unroll
            for (int mt = 0; mt < 2; mt++)
                #pragma unroll
                for (int nt = 0; nt < 8; nt++) {
                    mma_bf16(acc[mt][nt], a_h[mt], b_h[nt][0], b_h[nt][1]);
                    mma_bf16(acc[mt][nt], a_h[mt], b_l[nt][0], b_l[nt][1]);
                    mma_bf16(acc[mt][nt], a_l[mt], b_h[nt][0], b_h[nt][1]);
                }
        }
        __syncthreads();
    }

    #pragma unroll
    for (int mt = 0; mt < 2; mt++) {
        #pragma unroll
        for (int half = 0; half < 2; half++) {
            int r = m0 + warp_m * 32 + mt * 16 + (lane >> 2) + half * 8;
            size_t crow = (size_t)r * ldc;
            #pragma unroll
            for (int nt = 0; nt < 8; nt++) {
                int c = n0 + warp_n * 64 + nt * 8 + (lane & 3) * 2;
                float2 v;
                v.x = acc[mt][nt][half * 2 + 0];
                v.y = acc[mt][nt][half * 2 + 1];
                if (bias) { v.x += bias[c]; v.y += bias[c + 1]; }
                if (add) {
                    float2 a = *(const float2*)&add[crow + c];
                    v.x += a.x; v.y += a.y;
                }
                if (Ohi) {
                    if (c < qscale_cols) { v.x *= 0.125f; v.y *= 0.125f; }
                    uint32_t hp = pack_bf16(v.x, v.y);
                    *(uint32_t*)&Ohi[crow + c] = hp;
                    __nv_bfloat16* hb = (__nv_bfloat16*)&hp;
                    *(uint32_t*)&Olo[crow + c] = pack_bf16(v.x - __bfloat162float(hb[0]),
                                                           v.y - __bfloat162float(hb[1]));
                } else {
                    *(float2*)&C[crow + c] = v;
                }
            }
        }
    }
}

// ---------------- fused gate/up GEMM + SwiGLU + split (1 CTA/SM, 4 stages) ----
#define MSTAGES 4
#define MTILEB 8192
#define MSTGB (6*MTILEB)
#define MLP_SMEM (MSTAGES*MSTGB)   // 196608

__global__ __launch_bounds__(256, 1)
void tc_gemm_swiglu(const __nv_bfloat16* __restrict__ Ahi, const __nv_bfloat16* __restrict__ Alo,
                    const __nv_bfloat16* __restrict__ Whi, const __nv_bfloat16* __restrict__ Wlo,
                    __nv_bfloat16* __restrict__ Ohi, __nv_bfloat16* __restrict__ Olo)
{
    extern __shared__ __align__(1024) char smem[];
    uint32_t sb = smem_u32(smem);
    int tid = threadIdx.x, wid = tid >> 5, lane = tid & 31;
    int m0 = blockIdx.y * 128, n0 = blockIdx.x * 128;
    int warp_m = wid & 3, warp_n = wid >> 2;

    const int K = DD;
    const int KT = K / GBK;

    auto issue_loads = [&](int s, int kt){
        int k0 = kt * GBK;
        uint32_t stg = sb + s * MSTGB;
        #pragma unroll
        for (int t = 0; t < 6; t++) {
            const __nv_bfloat16* src =
                (t == 0 ? Ahi : t == 1 ? Alo : t == 2 ? Whi : t == 3 ? Wlo : t == 4 ? Whi : Wlo);
            int rb = (t < 2 ? m0 : (t < 4 ? n0 : IPAD + n0));
            #pragma unroll
            for (int i = 0; i < 2; i++) {
                int id = i * 256 + tid;
                int r = id >> 2, c = id & 3;
                const void* g = src + (size_t)(rb + r) * K + k0 + c * 8;
                uint32_t d = stg + t * MTILEB + SWZ64((uint32_t)(r * 64 + c * 16));
                CPA16(d, g);
            }
        }
        CPA_COMMIT();
    };

    float accg[2][8][4], accu[2][8][4];
    #pragma unroll
    for (int mt = 0; mt < 2; mt++)
        #pragma unroll
        for (int nt = 0; nt < 8; nt++)
            #pragma unroll
            for (int i = 0; i < 4; i++) { accg[mt][nt][i] = 0.0f; accu[mt][nt][i] = 0.0f; }

    issue_loads(0, 0);
    issue_loads(1, 1);
    issue_loads(2, 2);

    for (int kt = 0; kt < KT; kt++) {
        asm volatile("cp.async.wait_group 2;\n" ::: "memory");
        __syncthreads();
        if (kt + 3 < KT) issue_loads((kt + 3) % MSTAGES, kt + 3);

        uint32_t stg = sb + (kt % MSTAGES) * MSTGB;
        #pragma unroll
        for (int kk = 0; kk < 2; kk++) {
            uint32_t a_h[2][4], a_l[2][4];
            #pragma unroll
            for (int mt = 0; mt < 2; mt++) {
                int row = warp_m * 32 + mt * 16 + (lane & 15);
                uint32_t sw = SWZ64((uint32_t)(row * 64 + kk * 32 + (lane >> 4) * 16));
                ldsm_x4(a_h[mt], stg + sw);
                ldsm_x4(a_l[mt], stg + MTILEB + sw);
            }
            #pragma unroll
            for (int gu = 0; gu < 2; gu++) {
                uint32_t bh_off = stg + (2 + 2 * gu) * MTILEB;
                uint32_t bl_off = stg + (3 + 2 * gu) * MTILEB;
                #pragma unroll
                for (int np = 0; np < 4; np++) {
                    int nrow = warp_n * 64 + np * 16 + (lane & 7) + ((lane >> 4) << 3);
                    uint32_t sw = SWZ64((uint32_t)(nrow * 64 + kk * 32 + ((lane >> 3) & 1) * 16));
                    uint32_t th[4], tl[4];
                    ldsm_x4(th, bh_off + sw);
                    ldsm_x4(tl, bl_off + sw);
                    #pragma unroll
                    for (int mt = 0; mt < 2; mt++) {
                        float* c0 = (gu == 0 ? accg[mt][2*np]   : accu[mt][2*np]);
                        float* c1 = (gu == 0 ? accg[mt][2*np+1] : accu[mt][2*np+1]);
                        mma_bf16(c0, a_h[mt], th[0], th[1]);
                        mma_bf16(c0, a_h[mt], tl[0], tl[1]);
                        mma_bf16(c0, a_l[mt], th[0], th[1]);
                        mma_bf16(c1, a_h[mt], th[2], th[3]);
                        mma_bf16(c1, a_h[mt], tl[2], tl[3]);
                        mma_bf16(c1, a_l[mt], th[2], th[3]);
                    }
                }
            }
        }
        __syncthreads();
    }

    #pragma unroll
    for (int mt = 0; mt < 2; mt++) {
        #pragma unroll
        for (int half = 0; half < 2; half++) {
            int r = m0 + warp_m * 32 + mt * 16 + (lane >> 2) + half * 8;
            size_t crow = (size_t)r * IPAD;
            #pragma unroll
            for (int nt = 0; nt < 8; nt++) {
                int c = n0 + warp_n * 64 + nt * 8 + (lane & 3) * 2;
                float g0 = accg[mt][nt][half * 2 + 0];
                float g1 = accg[mt][nt][half * 2 + 1];
                float u0 = accu[mt][nt][half * 2 + 0];
                float u1 = accu[mt][nt][half * 2 + 1];
                float v0 = g0 / (1.0f + __expf(-g0)) * u0;
                float v1 = g1 / (1.0f + __expf(-g1)) * u1;
                uint32_t hp = pack_bf16(v0, v1);
                *(uint32_t*)&Ohi[crow + c] = hp;
                __nv_bfloat16* hb = (__nv_bfloat16*)&hp;
                *(uint32_t*)&Olo[crow + c] = pack_bf16(v0 - __bfloat162float(hb[0]),
                                                       v1 - __bfloat162float(hb[1]));
            }
        }
    }
}

// ---------------- FA2-style HMMA attention (heavy-first schedule) ----------
#define AQ 128
#define AK 64
#define SM_QHI 0
#define SM_QLO 16384
#define SM_KV  32768
#define SO_KHI 0
#define SO_KLO 8192
#define SO_VHI 16384
#define SO_VLO 24576
#define KV_STG 32768
#define SM_KPM (SM_KV + 2*KV_STG)
#define ATTN_SMEM (SM_KPM + 128)

__global__ __launch_bounds__(256, 1)
void attn_mma_kernel(const __nv_bfloat16* __restrict__ qkv_hi,
                     const __nv_bfloat16* __restrict__ qkv_lo,
                     const unsigned char* __restrict__ kpm,
                     __nv_bfloat16* __restrict__ ohi, __nv_bfloat16* __restrict__ olo)
{
    extern __shared__ __align__(1024) char smem[];
    uint32_t sb = smem_u32(smem);
    int tid = threadIdx.x, wid = tid >> 5, lane = tid & 31;
    // heavy-first: large qt (most KV tiles) launches earliest
    int qt = (int)gridDim.x - 1 - (int)blockIdx.x;
    int bh = blockIdx.y;
    int b = bh >> 4, h = bh & 15;
    size_t row0 = (size_t)(b * SS + qt * AQ);

    auto issue_kv = [&](int t){
        int s = t & 1;
        int j0 = t * AK;
        uint32_t stg = sb + SM_KV + s * KV_STG;
        #pragma unroll
        for (int i = 0; i < 2; i++) {
            int id = i * 256 + tid;
            int r = id >> 3, c = id & 7;
            size_t g = (size_t)(b * SS + j0 + r) * QKVN + h * HDD + c * 8;
            uint32_t sw = SWZ128((uint32_t)(r * 128 + c * 16));
            CPA16(stg + SO_KHI + sw, qkv_hi + g + 1024);
            CPA16(stg + SO_KLO + sw, qkv_lo + g + 1024);
            CPA16(stg + SO_VHI + sw, qkv_hi + g + 2048);
            CPA16(stg + SO_VLO + sw, qkv_lo + g + 2048);
        }
        if (tid < 4)
            CPA16(sb + SM_KPM + s * 64 + tid * 16, kpm + (size_t)b * SS + j0 + tid * 16);
        CPA_COMMIT();
    };

    const int T = 2 * qt + 2;

    issue_kv(0);
    #pragma unroll
    for (int i = 0; i < 4; i++) {
        int id = i * 256 + tid;
        int r = id >> 3, c = id & 7;
        size_t g = (row0 + r) * QKVN + h * HDD + c * 8;
        uint32_t sw = SWZ128((uint32_t)(r * 128 + c * 16));
        CPA16(sb + SM_QHI + sw, qkv_hi + g);
        CPA16(sb + SM_QLO + sw, qkv_lo + g);
    }
    CPA_COMMIT();
    issue_kv(1);

    asm volatile("cp.async.wait_group 1;\n" ::: "memory");
    __syncthreads();

    uint32_t qh[4][4], ql[4][4];
    {
        int row = wid * 16 + (lane & 15);
        #pragma unroll
        for (int kk = 0; kk < 4; kk++) {
            uint32_t sw = SWZ128((uint32_t)(row * 128 + kk * 32 + (lane >> 4) * 16));
            ldsm_x4(qh[kk], sb + SM_QHI + sw);
            ldsm_x4(ql[kk], sb + SM_QLO + sw);
        }
    }

    float slope = -exp2f(-0.5f * (float)(h + 1));
    float m[2] = {-1e30f, -1e30f}, l[2] = {0.0f, 0.0f};
    float o[8][4];
    #pragma unroll
    for (int nt = 0; nt < 8; nt++)
        #pragma unroll
        for (int i = 0; i < 4; i++) o[nt][i] = 0.0f;

    int r0 = wid * 16 + (lane >> 2);

    for (int t = 0; t < T; t++) {
        if (t > 0) {
            asm volatile("cp.async.wait_group 1;\n" ::: "memory");
            __syncthreads();
        }
        uint32_t stg = sb + SM_KV + (t & 1) * KV_STG;
        const unsigned char* kpms = (const unsigned char*)(smem + SM_KPM + (t & 1) * 64);
        int j0 = t * AK;
        bool diag = (t >= 2 * qt);

        float s[8][4];
        #pragma unroll
        for (int nt = 0; nt < 8; nt++)
            #pragma unroll
            for (int i = 0; i < 4; i++) s[nt][i] = 0.0f;

        #pragma unroll
        for (int kk = 0; kk < 4; kk++) {
            #pragma unroll
            for (int np = 0; np < 4; np++) {
                int nrow = np * 16 + (lane & 7) + ((lane >> 4) << 3);
                uint32_t sw = SWZ128((uint32_t)(nrow * 128 + kk * 32 + ((lane >> 3) & 1) * 16));
                uint32_t bhh[4], bll[4];
                ldsm_x4(bhh, stg + SO_KHI + sw);
                ldsm_x4(bll, stg + SO_KLO + sw);
                mma_bf16(s[2*np],   qh[kk], bhh[0], bhh[1]);
                mma_bf16(s[2*np],   qh[kk], bll[0], bll[1]);
                mma_bf16(s[2*np],   ql[kk], bhh[0], bhh[1]);
                mma_bf16(s[2*np+1], qh[kk], bhh[2], bhh[3]);
                mma_bf16(s[2*np+1], qh[kk], bll[2], bll[3]);
                mma_bf16(s[2*np+1], ql[kk], bhh[2], bhh[3]);
            }
        }

        float mt[2] = {-1e30f, -1e30f};
        #pragma unroll
        for (int nt = 0; nt < 8; nt++) {
            #pragma unroll
            for (int i = 0; i < 4; i++) {
                int half = i >> 1;
                int qi = qt * AQ + r0 + half * 8;
                int jj = j0 + nt * 8 + (lane & 3) * 2 + (i & 1);
                float sc = s[nt][i] + slope * fabsf((float)(qi - jj));
                if ((diag && jj > qi) || kpms[jj - j0]) sc = -1e30f;
                s[nt][i] = sc;
                mt[half] = fmaxf(mt[half], sc);
            }
        }
        #pragma unroll
        for (int half = 0; half < 2; half++) {
            mt[half] = fmaxf(mt[half], __shfl_xor_sync(0xffffffffu, mt[half], 1));
            mt[half] = fmaxf(mt[half], __shfl_xor_sync(0xffffffffu, mt[half], 2));
            float mnew = fmaxf(m[half], mt[half]);
            float corr = __expf(m[half] - mnew);
            m[half] = mnew;
            l[half] *= corr;
            #pragma unroll
            for (int nt = 0; nt < 8; nt++) {
                o[nt][half*2 + 0] *= corr;
                o[nt][half*2 + 1] *= corr;
            }
        }
        #pragma unroll
        for (int nt = 0; nt < 8; nt++) {
            #pragma unroll
            for (int i = 0; i < 4; i++) {
                float p = __expf(s[nt][i] - m[i >> 1]);
                s[nt][i] = p;
                l[i >> 1] += p;
            }
        }

        #pragma unroll
        for (int kc = 0; kc < 4; kc++) {
            uint32_t ph[4], pl[4];
            #pragma unroll
            for (int idx = 0; idx < 4; idx++) {
                int nt = 2 * kc + (idx >> 1);
                int ci = (idx & 1) * 2;
                float v0 = s[nt][ci], v1 = s[nt][ci + 1];
                ph[idx] = pack_bf16(v0, v1);
                __nv_bfloat16* hp = (__nv_bfloat16*)&ph[idx];
                pl[idx] = pack_bf16(v0 - __bfloat162float(hp[0]),
                                    v1 - __bfloat162float(hp[1]));
            }
            #pragma unroll
            for (int np = 0; np < 4; np++) {
                uint32_t sw = SWZ128((uint32_t)((kc * 16 + (lane & 15)) * 128 + np * 32 + (lane >> 4) * 16));
                uint32_t vh[4], vl[4];
                ldsm_x4_t(vh, stg + SO_VHI + sw);
                ldsm_x4_t(vl, stg + SO_VLO + sw);
                mma_bf16(o[2*np],   ph, vh[0], vh[1]);
                mma_bf16(o[2*np],   ph, vl[0], vl[1]);
                mma_bf16(o[2*np],   pl, vh[0], vh[1]);
                mma_bf16(o[2*np+1], ph, vh[2], vh[3]);
                mma_bf16(o[2*np+1], ph, vl[2], vl[3]);
                mma_bf16(o[2*np+1], pl, vh[2], vh[3]);
            }
        }

        __syncthreads();
        if (t + 2 < T) issue_kv(t + 2);
    }

    float inv[2];
    #pragma unroll
    for (int half = 0; half < 2; half++) {
        float ls = l[half];
        ls += __shfl_xor_sync(0xffffffffu, ls, 1);
        ls += __shfl_xor_sync(0xffffffffu, ls, 2);
        inv[half] = 1.0f / ls;
    }
    #pragma unroll
    for (int nt = 0; nt < 8; nt++) {
        #pragma unroll
        for (int half = 0; half < 2; half++) {
            int row = qt * AQ + wid * 16 + (lane >> 2) + half * 8;
            int col = h * HDD + nt * 8 + (lane & 3) * 2;
            size_t off = (size_t)(b * SS + row) * DD + col;
            float v0 = o[nt][half*2 + 0] * inv[half];
            float v1 = o[nt][half*2 + 1] * inv[half];
            uint32_t hp = pack_bf16(v0, v1);
            *(uint32_t*)&ohi[off] = hp;
            __nv_bfloat16* hb = (__nv_bfloat16*)&hp;
            *(uint32_t*)&olo[off] = pack_bf16(v0 - __bfloat162float(hb[0]),
                                              v1 - __bfloat162float(hb[1]));
        }
    }
}

// ---------------- RMSNorm + split ----------------
__global__ __launch_bounds__(256)
void rmsnorm_split_kernel(const float* __restrict__ x, const float* __restrict__ w,
                          __nv_bfloat16* __restrict__ ohi, __nv_bfloat16* __restrict__ olo)
{
    int row = blockIdx.x;
    const float* xr = x + (size_t)row * DD;
    int t = threadIdx.x;

    float v0 = xr[t], v1 = xr[t + 256], v2 = xr[t + 512], v3 = xr[t + 768];
    float ss = v0*v0 + v1*v1 + v2*v2 + v3*v3;
    #pragma unroll
    for (int off = 16; off; off >>= 1) ss += __shfl_xor_sync(0xffffffffu, ss, off);
    __shared__ float red[8];
    int wid = t >> 5, lid = t & 31;
    if (lid == 0) red[wid] = ss;
    __syncthreads();
    float tot = red[0]+red[1]+red[2]+red[3]+red[4]+red[5]+red[6]+red[7];
    float inv = rsqrtf(tot * (1.0f / (float)DD) + 1e-6f);

    size_t base = (size_t)row * DD;
    #pragma unroll
    for (int i = 0; i < 4; i++) {
        int c = t + i * 256;
        float val = w[c] * (i==0?v0:i==1?v1:i==2?v2:v3) * inv;
        __nv_bfloat16 hi = __float2bfloat16(val);
        ohi[base + c] = hi;
        olo[base + c] = __float2bfloat16(val - __bfloat162float(hi));
    }
}

// ---------------- all weight transposes + bias concat in ONE launch ----------
struct TJob { const float* src; __nv_bfloat16* dhi; __nv_bfloat16* dlo;
              int Ks, Ns, Kout, Npad; };

__global__ __launch_bounds__(256)
void tsplit_all_kernel(TJob j0, TJob j1, TJob j2, TJob j3, TJob j4, TJob j5, TJob j6,
                       const float* __restrict__ bq, const float* __restrict__ bk,
                       const float* __restrict__ bv, float* __restrict__ bqkv)
{
    TJob jobs[7] = { j0, j1, j2, j3, j4, j5, j6 };
    int jz = blockIdx.z;
    TJob jb = jobs[jz];
    int kt = blockIdx.x * 32, nt = blockIdx.y * 32;

    if (jz == 0 && blockIdx.x == 0 && blockIdx.y < 12) {
        int i = blockIdx.y * 256 + threadIdx.x;
        if (i < 1024)       bqkv[i] = bq[i];
        else if (i < 2048)  bqkv[i] = bk[i - 1024];
        else if (i < 3072)  bqkv[i] = bv[i - 2048];
    }

    if (kt >= jb.Kout || nt >= jb.Npad) return;

    __shared__ float ts[32][33];
    int tx = threadIdx.x & 31, ty = threadIdx.x >> 5;
    #pragma unroll
    for (int i = 0; i < 4; i++) {
        int k = kt + ty + 8 * i, n = nt + tx;
        ts[ty + 8 * i][tx] = (k < jb.Ks && n < jb.Ns) ? jb.src[(size_t)k * jb.Ns + n] : 0.0f;
    }
    __syncthreads();
    #pragma unroll
    for (int i = 0; i < 4; i++) {
        int n = nt + ty + 8 * i, k = kt + tx;
        if (n >= jb.Npad || k >= jb.Kout) continue;
        float v = ts[tx][ty + 8 * i];
        __nv_bfloat16 hi = __float2bfloat16(v);
        jb.dhi[(size_t)n * jb.Kout + k] = hi;
        jb.dlo[(size_t)n * jb.Kout + k] = __float2bfloat16(v - __bfloat162float(hi));
    }
}

// ---------------- launch ----------------
extern "C" void kernel_launch(void* const* d_in, const int* in_sizes, int n_in,
                              void* d_out, int out_size)
{
    const float* x      = (const float*)d_in[0];
    const float* wq     = (const float*)d_in[1];
    const float* bq     = (const float*)d_in[2];
    const float* wk     = (const float*)d_in[3];
    const float* bk     = (const float*)d_in[4];
    const float* wv     = (const float*)d_in[5];
    const float* bv     = (const float*)d_in[6];
    const float* wo     = (const float*)d_in[7];
    const float* bo     = (const float*)d_in[8];
    const float* w_gate = (const float*)d_in[9];
    const float* w_up   = (const float*)d_in[10];
    const float* w_down = (const float*)d_in[11];
    const float* ln1w   = (const float*)d_in[12];
    const float* ln2w   = (const float*)d_in[13];
    const unsigned char* kpm = (const unsigned char*)d_in[16];
    float* out = (float*)d_out;

    __nv_bfloat16 *h_hi, *h_lo, *qkv_hi, *qkv_lo, *attn_hi, *attn_lo, *h2_hi, *h2_lo, *act_hi, *act_lo;
    __nv_bfloat16 *wqkvT_hi, *wqkvT_lo, *woT_hi, *woT_lo, *wguT_hi, *wguT_lo, *wdT_hi, *wdT_lo;
    float *res1, *bqkv;
    cudaGetSymbolAddress((void**)&h_hi, g_h_hi);     cudaGetSymbolAddress((void**)&h_lo, g_h_lo);
    cudaGetSymbolAddress((void**)&qkv_hi, g_qkv_hi); cudaGetSymbolAddress((void**)&qkv_lo, g_qkv_lo);
    cudaGetSymbolAddress((void**)&attn_hi, g_attn_hi); cudaGetSymbolAddress((void**)&attn_lo, g_attn_lo);
    cudaGetSymbolAddress((void**)&res1, g_res1);
    cudaGetSymbolAddress((void**)&h2_hi, g_h2_hi);   cudaGetSymbolAddress((void**)&h2_lo, g_h2_lo);
    cudaGetSymbolAddress((void**)&act_hi, g_act_hi); cudaGetSymbolAddress((void**)&act_lo, g_act_lo);
    cudaGetSymbolAddress((void**)&wqkvT_hi, g_wqkvT_hi); cudaGetSymbolAddress((void**)&wqkvT_lo, g_wqkvT_lo);
    cudaGetSymbolAddress((void**)&woT_hi, g_woT_hi); cudaGetSymbolAddress((void**)&woT_lo, g_woT_lo);
    cudaGetSymbolAddress((void**)&wguT_hi, g_wguT_hi); cudaGetSymbolAddress((void**)&wguT_lo, g_wguT_lo);
    cudaGetSymbolAddress((void**)&wdT_hi, g_wdT_hi); cudaGetSymbolAddress((void**)&wdT_lo, g_wdT_lo);
    cudaGetSymbolAddress((void**)&bqkv, g_bqkv);

    cudaFuncSetAttribute(tc_gemm, cudaFuncAttributeMaxDynamicSharedMemorySize, GEMM_SMEM);
    cudaFuncSetAttribute(tc_gemm_swiglu, cudaFuncAttributeMaxDynamicSharedMemorySize, MLP_SMEM);
    cudaFuncSetAttribute(attn_mma_kernel, cudaFuncAttributeMaxDynamicSharedMemorySize, ATTN_SMEM);

    // launch 0: ALL weight prep in one kernel
    {
        //            src      dhi                     dlo                     Ks    Ns    Kout  Npad
        TJob j0 = { wq,     wqkvT_hi,               wqkvT_lo,               1024, 1024, 1024, 1024 };
        TJob j1 = { wk,     wqkvT_hi + 1024*1024,   wqkvT_lo + 1024*1024,   1024, 1024, 1024, 1024 };
        TJob j2 = { wv,     wqkvT_hi + 2048*1024,   wqkvT_lo + 2048*1024,   1024, 1024, 1024, 1024 };
        TJob j3 = { wo,     woT_hi,                 woT_lo,                 1024, 1024, 1024, 1024 };
        TJob j4 = { w_gate, wguT_hi,                wguT_lo,                1024, II,   1024, IPAD };
        TJob j5 = { w_up,   wguT_hi + IPAD*1024,    wguT_lo + IPAD*1024,    1024, II,   1024, IPAD };
        TJob j6 = { w_down, wdT_hi,                 wdT_lo,                 II,   1024, IPAD, 1024 };
        tsplit_all_kernel<<<dim3(120, 120, 7), 256>>>(j0, j1, j2, j3, j4, j5, j6,
                                                      bq, bk, bv, bqkv);
    }
    // launch 1: h = rmsnorm(x) -> hi/lo
    rmsnorm_split_kernel<<<MM, 256>>>(x, ln1w, h_hi, h_lo);
    // launch 2: qkv GEMM
    tc_gemm<<<dim3(QKVN / 128, MM / 128), 256, GEMM_SMEM>>>(h_hi, h_lo, wqkvT_hi, wqkvT_lo,
        bqkv, nullptr, nullptr, DD, QKVN, qkv_hi, qkv_lo, 1024);
    // launch 3: attention (heavy-first schedule)
    attn_mma_kernel<<<dim3(SS / AQ, BB * HH), 256, ATTN_SMEM>>>(qkv_hi, qkv_lo, kpm, attn_hi, attn_lo);
    // launch 4: res1 = attn @ Wo^T + bo + x
    tc_gemm<<<dim3(DD / 128, MM / 128), 256, GEMM_SMEM>>>(attn_hi, attn_lo, woT_hi, woT_lo,
        bo, x, res1, DD, DD, nullptr, nullptr, 0);
    // launch 5: h2 = rmsnorm(res1)
    rmsnorm_split_kernel<<<MM, 256>>>(res1, ln2w, h2_hi, h2_lo);
    // launch 6: fused swiglu GEMM
    tc_gemm_swiglu<<<dim3(IPAD / 128, MM / 128), 256, MLP_SMEM>>>(h2_hi, h2_lo,
        wguT_hi, wguT_lo, act_hi, act_lo);
    // launch 7: out = act @ Wdown^T + res1
    tc_gemm<<<dim3(DD / 128, MM / 128), 256, GEMM_SMEM>>>(act_hi, act_lo, wdT_hi, wdT_lo,
        nullptr, res1, out, IPAD, DD, nullptr, nullptr, 0);

    (void)in_sizes; (void)n_in; (void)out_size;
}

// round 14
// speedup vs baseline: 1.5495x; 1.5495x over previous
#include <cuda_runtime.h>
#include <cuda_bf16.h>
#include <math.h>
#include <stdint.h>

// ---------------- problem dims ----------------
#define BB 2
#define SS 2048
#define DD 1024
#define HH 16
#define HDD 64
#define II 3752
#define MM (BB*SS)          // 4096
#define QKVN 3072
#define IPAD 3840
#define GUN (2*IPAD)        // 7680

// ---------------- scratch ----------------
__device__ __nv_bfloat16 g_h_hi[MM*DD],  g_h_lo[MM*DD];
__device__ __nv_bfloat16 g_qkv_hi[(size_t)MM*QKVN], g_qkv_lo[(size_t)MM*QKVN];
__device__ __nv_bfloat16 g_attn_hi[MM*DD], g_attn_lo[MM*DD];
__device__ float         g_res1[MM*DD];
__device__ __nv_bfloat16 g_h2_hi[MM*DD], g_h2_lo[MM*DD];
__device__ __nv_bfloat16 g_act_hi[(size_t)MM*IPAD], g_act_lo[(size_t)MM*IPAD];
__device__ __nv_bfloat16 g_wqkvT_hi[QKVN*DD], g_wqkvT_lo[QKVN*DD];
__device__ __nv_bfloat16 g_woT_hi[DD*DD],     g_woT_lo[DD*DD];
__device__ __nv_bfloat16 g_wguT_hi[GUN*DD],   g_wguT_lo[GUN*DD];
__device__ __nv_bfloat16 g_wdT_hi[DD*IPAD],   g_wdT_lo[DD*IPAD];
__device__ float         g_bqkv[QKVN];

// ---------------- helpers ----------------
__device__ __forceinline__ uint32_t smem_u32(const void* p){
    uint32_t r;
    asm("{ .reg .u64 t; cvta.to.shared.u64 t, %1; cvt.u32.u64 %0, t; }" : "=r"(r) : "l"(p));
    return r;
}
#define SWZ64(x)  ((x) ^ (((x) >> 3) & 0x30))
#define SWZ128(x) ((x) ^ (((x) >> 3) & 0x70))

__device__ __forceinline__ void ldsm_x4(uint32_t* r, uint32_t a){
    asm volatile("ldmatrix.sync.aligned.m8n8.x4.shared.b16 {%0,%1,%2,%3}, [%4];"
        : "=r"(r[0]), "=r"(r[1]), "=r"(r[2]), "=r"(r[3]) : "r"(a));
}
__device__ __forceinline__ void ldsm_x4_t(uint32_t* r, uint32_t a){
    asm volatile("ldmatrix.sync.aligned.m8n8.x4.trans.shared.b16 {%0,%1,%2,%3}, [%4];"
        : "=r"(r[0]), "=r"(r[1]), "=r"(r[2]), "=r"(r[3]) : "r"(a));
}
__device__ __forceinline__ void mma_bf16(float* c, const uint32_t* a, uint32_t b0, uint32_t b1){
    asm volatile("mma.sync.aligned.m16n8k16.row.col.f32.bf16.bf16.f32 "
        "{%0,%1,%2,%3}, {%4,%5,%6,%7}, {%8,%9}, {%0,%1,%2,%3};"
        : "+f"(c[0]), "+f"(c[1]), "+f"(c[2]), "+f"(c[3])
        : "r"(a[0]), "r"(a[1]), "r"(a[2]), "r"(a[3]), "r"(b0), "r"(b1));
}
__device__ __forceinline__ uint32_t pack_bf16(float lo_elem, float hi_elem){
    uint32_t r;
    asm("cvt.rn.bf16x2.f32 %0, %1, %2;" : "=r"(r) : "f"(hi_elem), "f"(lo_elem));
    return r;
}
#define CPA16(d, g) asm volatile("cp.async.cg.shared.global [%0], [%1], 16;\n" :: "r"(d), "l"(g))
#define CPA_COMMIT() asm volatile("cp.async.commit_group;\n" ::: "memory")

// ---------------- HMMA GEMM (R8-proven: 4 stages, 1 CTA/SM) ----------------
#define GBK 32
#define STAGES 4
#define TILEB (128*32*2)
#define STGB (4*TILEB)
#define GEMM_SMEM (STAGES*STGB)    // 131072

__global__ __launch_bounds__(256, 1)
void tc_gemm(const __nv_bfloat16* __restrict__ Ahi, const __nv_bfloat16* __restrict__ Alo,
             const __nv_bfloat16* __restrict__ Bhi, const __nv_bfloat16* __restrict__ Blo,
             const float* __restrict__ bias, const float* __restrict__ add,
             float* __restrict__ C, int K, int ldc,
             __nv_bfloat16* __restrict__ Ohi, __nv_bfloat16* __restrict__ Olo, int qscale_cols)
{
    extern __shared__ __align__(1024) char smem[];
    uint32_t sb = smem_u32(smem);
    int tid = threadIdx.x, wid = tid >> 5, lane = tid & 31;
    int m0 = blockIdx.y * 128, n0 = blockIdx.x * 128;
    int warp_m = wid & 3, warp_n = wid >> 2;

    const int KT = K / GBK;

    auto issue_loads = [&](int s, int kt){
        int k0 = kt * GBK;
        uint32_t stg = sb + s * STGB;
        #pragma unroll
        for (int t = 0; t < 4; t++) {
            const __nv_bfloat16* src = (t == 0 ? Ahi : t == 1 ? Alo : t == 2 ? Bhi : Blo);
            int rb = (t < 2 ? m0 : n0);
            #pragma unroll
            for (int i = 0; i < 2; i++) {
                int id = i * 256 + tid;
                int r = id >> 2, c = id & 3;
                const void* g = src + (size_t)(rb + r) * K + k0 + c * 8;
                uint32_t d = stg + t * TILEB + SWZ64((uint32_t)(r * 64 + c * 16));
                CPA16(d, g);
            }
        }
        CPA_COMMIT();
    };

    float acc[2][8][4];
    #pragma unroll
    for (int mt = 0; mt < 2; mt++)
        #pragma unroll
        for (int nt = 0; nt < 8; nt++)
            #pragma unroll
            for (int i = 0; i < 4; i++) acc[mt][nt][i] = 0.0f;

    issue_loads(0, 0);
    issue_loads(1, 1);
    issue_loads(2, 2);

    for (int kt = 0; kt < KT; kt++) {
        asm volatile("cp.async.wait_group 2;\n" ::: "memory");
        __syncthreads();
        if (kt + 3 < KT) issue_loads((kt + 3) % STAGES, kt + 3);

        uint32_t stg = sb + (kt % STAGES) * STGB;
        #pragma unroll
        for (int kk = 0; kk < 2; kk++) {
            uint32_t a_h[2][4], a_l[2][4];
            #pragma unroll
            for (int mt = 0; mt < 2; mt++) {
                int row = warp_m * 32 + mt * 16 + (lane & 15);
                uint32_t sw = SWZ64((uint32_t)(row * 64 + kk * 32 + (lane >> 4) * 16));
                ldsm_x4(a_h[mt], stg + sw);
                ldsm_x4(a_l[mt], stg + TILEB + sw);
            }
            uint32_t b_h[8][2], b_l[8][2];
            #pragma unroll
            for (int np = 0; np < 4; np++) {
                int nrow = warp_n * 64 + np * 16 + (lane & 7) + ((lane >> 4) << 3);
                uint32_t sw = SWZ64((uint32_t)(nrow * 64 + kk * 32 + ((lane >> 3) & 1) * 16));
                uint32_t t4[4];
                ldsm_x4(t4, stg + 2 * TILEB + sw);
                b_h[2*np][0] = t4[0]; b_h[2*np][1] = t4[1];
                b_h[2*np+1][0] = t4[2]; b_h[2*np+1][1] = t4[3];
                ldsm_x4(t4, stg + 3 * TILEB + sw);
                b_l[2*np][0] = t4[0]; b_l[2*np][1] = t4[1];
                b_l[2*np+1][0] = t4[2]; b_l[2*np+1][1] = t4[3];
            }
            #pragma unroll
            for (int mt = 0; mt < 2; mt++)
                #pragma unroll
                for (int nt = 0; nt < 8; nt++) {
                    mma_bf16(acc[mt][nt], a_h[mt], b_h[nt][0], b_h[nt][1]);
                    mma_bf16(acc[mt][nt], a_h[mt], b_l[nt][0], b_l[nt][1]);
                    mma_bf16(acc[mt][nt], a_l[mt], b_h[nt][0], b_h[nt][1]);
                }
        }
        __syncthreads();
    }

    #pragma unroll
    for (int mt = 0; mt < 2; mt++) {
        #pragma unroll
        for (int half = 0; half < 2; half++) {
            int r = m0 + warp_m * 32 + mt * 16 + (lane >> 2) + half * 8;
            size_t crow = (size_t)r * ldc;
            #pragma unroll
            for (int nt = 0; nt < 8; nt++) {
                int c = n0 + warp_n * 64 + nt * 8 + (lane & 3) * 2;
                float2 v;
                v.x = acc[mt][nt][half * 2 + 0];
                v.y = acc[mt][nt][half * 2 + 1];
                if (bias) { v.x += bias[c]; v.y += bias[c + 1]; }
                if (add) {
                    float2 a = *(const float2*)&add[crow + c];
                    v.x += a.x; v.y += a.y;
                }
                if (Ohi) {
                    if (c < qscale_cols) { v.x *= 0.125f; v.y *= 0.125f; }
                    uint32_t hp = pack_bf16(v.x, v.y);
                    *(uint32_t*)&Ohi[crow + c] = hp;
                    __nv_bfloat16* hb = (__nv_bfloat16*)&hp;
                    *(uint32_t*)&Olo[crow + c] = pack_bf16(v.x - __bfloat162float(hb[0]),
                                                           v.y - __bfloat162float(hb[1]));
                } else {
                    *(float2*)&C[crow + c] = v;
                }
            }
        }
    }
}

// ---------------- fused gate/up GEMM + SwiGLU + split (1 CTA/SM, 4 stages) ----
#define MSTAGES 4
#define MTILEB 8192
#define MSTGB (6*MTILEB)
#define MLP_SMEM (MSTAGES*MSTGB)   // 196608

__global__ __launch_bounds__(256, 1)
void tc_gemm_swiglu(const __nv_bfloat16* __restrict__ Ahi, const __nv_bfloat16* __restrict__ Alo,
                    const __nv_bfloat16* __restrict__ Whi, const __nv_bfloat16* __restrict__ Wlo,
                    __nv_bfloat16* __restrict__ Ohi, __nv_bfloat16* __restrict__ Olo)
{
    extern __shared__ __align__(1024) char smem[];
    uint32_t sb = smem_u32(smem);
    int tid = threadIdx.x, wid = tid >> 5, lane = tid & 31;
    int m0 = blockIdx.y * 128, n0 = blockIdx.x * 128;
    int warp_m = wid & 3, warp_n = wid >> 2;

    const int K = DD;
    const int KT = K / GBK;

    auto issue_loads = [&](int s, int kt){
        int k0 = kt * GBK;
        uint32_t stg = sb + s * MSTGB;
        #pragma unroll
        for (int t = 0; t < 6; t++) {
            const __nv_bfloat16* src =
                (t == 0 ? Ahi : t == 1 ? Alo : t == 2 ? Whi : t == 3 ? Wlo : t == 4 ? Whi : Wlo);
            int rb = (t < 2 ? m0 : (t < 4 ? n0 : IPAD + n0));
            #pragma unroll
            for (int i = 0; i < 2; i++) {
                int id = i * 256 + tid;
                int r = id >> 2, c = id & 3;
                const void* g = src + (size_t)(rb + r) * K + k0 + c * 8;
                uint32_t d = stg + t * MTILEB + SWZ64((uint32_t)(r * 64 + c * 16));
                CPA16(d, g);
            }
        }
        CPA_COMMIT();
    };

    float accg[2][8][4], accu[2][8][4];
    #pragma unroll
    for (int mt = 0; mt < 2; mt++)
        #pragma unroll
        for (int nt = 0; nt < 8; nt++)
            #pragma unroll
            for (int i = 0; i < 4; i++) { accg[mt][nt][i] = 0.0f; accu[mt][nt][i] = 0.0f; }

    issue_loads(0, 0);
    issue_loads(1, 1);
    issue_loads(2, 2);

    for (int kt = 0; kt < KT; kt++) {
        asm volatile("cp.async.wait_group 2;\n" ::: "memory");
        __syncthreads();
        if (kt + 3 < KT) issue_loads((kt + 3) % MSTAGES, kt + 3);

        uint32_t stg = sb + (kt % MSTAGES) * MSTGB;
        #pragma unroll
        for (int kk = 0; kk < 2; kk++) {
            uint32_t a_h[2][4], a_l[2][4];
            #pragma unroll
            for (int mt = 0; mt < 2; mt++) {
                int row = warp_m * 32 + mt * 16 + (lane & 15);
                uint32_t sw = SWZ64((uint32_t)(row * 64 + kk * 32 + (lane >> 4) * 16));
                ldsm_x4(a_h[mt], stg + sw);
                ldsm_x4(a_l[mt], stg + MTILEB + sw);
            }
            #pragma unroll
            for (int gu = 0; gu < 2; gu++) {
                uint32_t bh_off = stg + (2 + 2 * gu) * MTILEB;
                uint32_t bl_off = stg + (3 + 2 * gu) * MTILEB;
                #pragma unroll
                for (int np = 0; np < 4; np++) {
                    int nrow = warp_n * 64 + np * 16 + (lane & 7) + ((lane >> 4) << 3);
                    uint32_t sw = SWZ64((uint32_t)(nrow * 64 + kk * 32 + ((lane >> 3) & 1) * 16));
                    uint32_t th[4], tl[4];
                    ldsm_x4(th, bh_off + sw);
                    ldsm_x4(tl, bl_off + sw);
                    #pragma unroll
                    for (int mt = 0; mt < 2; mt++) {
                        float* c0 = (gu == 0 ? accg[mt][2*np]   : accu[mt][2*np]);
                        float* c1 = (gu == 0 ? accg[mt][2*np+1] : accu[mt][2*np+1]);
                        mma_bf16(c0, a_h[mt], th[0], th[1]);
                        mma_bf16(c0, a_h[mt], tl[0], tl[1]);
                        mma_bf16(c0, a_l[mt], th[0], th[1]);
                        mma_bf16(c1, a_h[mt], th[2], th[3]);
                        mma_bf16(c1, a_h[mt], tl[2], tl[3]);
                        mma_bf16(c1, a_l[mt], th[2], th[3]);
                    }
                }
            }
        }
        __syncthreads();
    }

    #pragma unroll
    for (int mt = 0; mt < 2; mt++) {
        #pragma unroll
        for (int half = 0; half < 2; half++) {
            int r = m0 + warp_m * 32 + mt * 16 + (lane >> 2) + half * 8;
            size_t crow = (size_t)r * IPAD;
            #pragma unroll
            for (int nt = 0; nt < 8; nt++) {
                int c = n0 + warp_n * 64 + nt * 8 + (lane & 3) * 2;
                float g0 = accg[mt][nt][half * 2 + 0];
                float g1 = accg[mt][nt][half * 2 + 1];
                float u0 = accu[mt][nt][half * 2 + 0];
                float u1 = accu[mt][nt][half * 2 + 1];
                float v0 = g0 / (1.0f + __expf(-g0)) * u0;
                float v1 = g1 / (1.0f + __expf(-g1)) * u1;
                uint32_t hp = pack_bf16(v0, v1);
                *(uint32_t*)&Ohi[crow + c] = hp;
                __nv_bfloat16* hb = (__nv_bfloat16*)&hp;
                *(uint32_t*)&Olo[crow + c] = pack_bf16(v0 - __bfloat162float(hb[0]),
                                                       v1 - __bfloat162float(hb[1]));
            }
        }
    }
}

// ---------------- FA2-style HMMA attention (heavy-first schedule) ----------
#define AQ 128
#define AK 64
#define SM_QHI 0
#define SM_QLO 16384
#define SM_KV  32768
#define SO_KHI 0
#define SO_KLO 8192
#define SO_VHI 16384
#define SO_VLO 24576
#define KV_STG 32768
#define SM_KPM (SM_KV + 2*KV_STG)
#define ATTN_SMEM (SM_KPM + 128)

__global__ __launch_bounds__(256, 1)
void attn_mma_kernel(const __nv_bfloat16* __restrict__ qkv_hi,
                     const __nv_bfloat16* __restrict__ qkv_lo,
                     const unsigned char* __restrict__ kpm,
                     __nv_bfloat16* __restrict__ ohi, __nv_bfloat16* __restrict__ olo)
{
    extern __shared__ __align__(1024) char smem[];
    uint32_t sb = smem_u32(smem);
    int tid = threadIdx.x, wid = tid >> 5, lane = tid & 31;
    // heavy-first: large qt (most KV tiles) launches earliest
    int qt = (int)gridDim.x - 1 - (int)blockIdx.x;
    int bh = blockIdx.y;
    int b = bh >> 4, h = bh & 15;
    size_t row0 = (size_t)(b * SS + qt * AQ);

    auto issue_kv = [&](int t){
        int s = t & 1;
        int j0 = t * AK;
        uint32_t stg = sb + SM_KV + s * KV_STG;
        #pragma unroll
        for (int i = 0; i < 2; i++) {
            int id = i * 256 + tid;
            int r = id >> 3, c = id & 7;
            size_t g = (size_t)(b * SS + j0 + r) * QKVN + h * HDD + c * 8;
            uint32_t sw = SWZ128((uint32_t)(r * 128 + c * 16));
            CPA16(stg + SO_KHI + sw, qkv_hi + g + 1024);
            CPA16(stg + SO_KLO + sw, qkv_lo + g + 1024);
            CPA16(stg + SO_VHI + sw, qkv_hi + g + 2048);
            CPA16(stg + SO_VLO + sw, qkv_lo + g + 2048);
        }
        if (tid < 4)
            CPA16(sb + SM_KPM + s * 64 + tid * 16, kpm + (size_t)b * SS + j0 + tid * 16);
        CPA_COMMIT();
    };

    const int T = 2 * qt + 2;

    issue_kv(0);
    #pragma unroll
    for (int i = 0; i < 4; i++) {
        int id = i * 256 + tid;
        int r = id >> 3, c = id & 7;
        size_t g = (row0 + r) * QKVN + h * HDD + c * 8;
        uint32_t sw = SWZ128((uint32_t)(r * 128 + c * 16));
        CPA16(sb + SM_QHI + sw, qkv_hi + g);
        CPA16(sb + SM_QLO + sw, qkv_lo + g);
    }
    CPA_COMMIT();
    issue_kv(1);

    asm volatile("cp.async.wait_group 1;\n" ::: "memory");
    __syncthreads();

    uint32_t qh[4][4], ql[4][4];
    {
        int row = wid * 16 + (lane & 15);
        #pragma unroll
        for (int kk = 0; kk < 4; kk++) {
            uint32_t sw = SWZ128((uint32_t)(row * 128 + kk * 32 + (lane >> 4) * 16));
            ldsm_x4(qh[kk], sb + SM_QHI + sw);
            ldsm_x4(ql[kk], sb + SM_QLO + sw);
        }
    }

    float slope = -exp2f(-0.5f * (float)(h + 1));
    float m[2] = {-1e30f, -1e30f}, l[2] = {0.0f, 0.0f};
    float o[8][4];
    #pragma unroll
    for (int nt = 0; nt < 8; nt++)
        #pragma unroll
        for (int i = 0; i < 4; i++) o[nt][i] = 0.0f;

    int r0 = wid * 16 + (lane >> 2);

    for (int t = 0; t < T; t++) {
        if (t > 0) {
            asm volatile("cp.async.wait_group 1;\n" ::: "memory");
            __syncthreads();
        }
        uint32_t stg = sb + SM_KV + (t & 1) * KV_STG;
        const unsigned char* kpms = (const unsigned char*)(smem + SM_KPM + (t & 1) * 64);
        int j0 = t * AK;
        bool diag = (t >= 2 * qt);

        float s[8][4];
        #pragma unroll
        for (int nt = 0; nt < 8; nt++)
            #pragma unroll
            for (int i = 0; i < 4; i++) s[nt][i] = 0.0f;

        #pragma unroll
        for (int kk = 0; kk < 4; kk++) {
            #pragma unroll
            for (int np = 0; np < 4; np++) {
                int nrow = np * 16 + (lane & 7) + ((lane >> 4) << 3);
                uint32_t sw = SWZ128((uint32_t)(nrow * 128 + kk * 32 + ((lane >> 3) & 1) * 16));
                uint32_t bhh[4], bll[4];
                ldsm_x4(bhh, stg + SO_KHI + sw);
                ldsm_x4(bll, stg + SO_KLO + sw);
                mma_bf16(s[2*np],   qh[kk], bhh[0], bhh[1]);
                mma_bf16(s[2*np],   qh[kk], bll[0], bll[1]);
                mma_bf16(s[2*np],   ql[kk], bhh[0], bhh[1]);
                mma_bf16(s[2*np+1], qh[kk], bhh[2], bhh[3]);
                mma_bf16(s[2*np+1], qh[kk], bll[2], bll[3]);
                mma_bf16(s[2*np+1], ql[kk], bhh[2], bhh[3]);
            }
        }

        float mt[2] = {-1e30f, -1e30f};
        #pragma unroll
        for (int nt = 0; nt < 8; nt++) {
            #pragma unroll
            for (int i = 0; i < 4; i++) {
                int half = i >> 1;
                int qi = qt * AQ + r0 + half * 8;
                int jj = j0 + nt * 8 + (lane & 3) * 2 + (i & 1);
                float sc = s[nt][i] + slope * fabsf((float)(qi - jj));
                if ((diag && jj > qi) || kpms[jj - j0]) sc = -1e30f;
                s[nt][i] = sc;
                mt[half] = fmaxf(mt[half], sc);
            }
        }
        #pragma unroll
        for (int half = 0; half < 2; half++) {
            mt[half] = fmaxf(mt[half], __shfl_xor_sync(0xffffffffu, mt[half], 1));
            mt[half] = fmaxf(mt[half], __shfl_xor_sync(0xffffffffu, mt[half], 2));
            float mnew = fmaxf(m[half], mt[half]);
            float corr = __expf(m[half] - mnew);
            m[half] = mnew;
            l[half] *= corr;
            #pragma unroll
            for (int nt = 0; nt < 8; nt++) {
                o[nt][half*2 + 0] *= corr;
                o[nt][half*2 + 1] *= corr;
            }
        }
        #pragma unroll
        for (int nt = 0; nt < 8; nt++) {
            #pragma unroll
            for (int i = 0; i < 4; i++) {
                float p = __expf(s[nt][i] - m[i >> 1]);
                s[nt][i] = p;
                l[i >> 1] += p;
            }
        }

        #pragma unroll
        for (int kc = 0; kc < 4; kc++) {
            uint32_t ph[4], pl[4];
            #pragma unroll
            for (int idx = 0; idx < 4; idx++) {
                int nt = 2 * kc + (idx >> 1);
                int ci = (idx & 1) * 2;
                float v0 = s[nt][ci], v1 = s[nt][ci + 1];
                ph[idx] = pack_bf16(v0, v1);
                __nv_bfloat16* hp = (__nv_bfloat16*)&ph[idx];
                pl[idx] = pack_bf16(v0 - __bfloat162float(hp[0]),
                                    v1 - __bfloat162float(hp[1]));
            }
            #pragma unroll
            for (int np = 0; np < 4; np++) {
                uint32_t sw = SWZ128((uint32_t)((kc * 16 + (lane & 15)) * 128 + np * 32 + (lane >> 4) * 16));
                uint32_t vh[4], vl[4];
                ldsm_x4_t(vh, stg + SO_VHI + sw);
                ldsm_x4_t(vl, stg + SO_VLO + sw);
                mma_bf16(o[2*np],   ph, vh[0], vh[1]);
                mma_bf16(o[2*np],   ph, vl[0], vl[1]);
                mma_bf16(o[2*np],   pl, vh[0], vh[1]);
                mma_bf16(o[2*np+1], ph, vh[2], vh[3]);
                mma_bf16(o[2*np+1], ph, vl[2], vl[3]);
                mma_bf16(o[2*np+1], pl, vh[2], vh[3]);
            }
        }

        __syncthreads();
        if (t + 2 < T) issue_kv(t + 2);
    }

    float inv[2];
    #pragma unroll
    for (int half = 0; half < 2; half++) {
        float ls = l[half];
        ls += __shfl_xor_sync(0xffffffffu, ls, 1);
        ls += __shfl_xor_sync(0xffffffffu, ls, 2);
        inv[half] = 1.0f / ls;
    }
    #pragma unroll
    for (int nt = 0; nt < 8; nt++) {
        #pragma unroll
        for (int half = 0; half < 2; half++) {
            int row = qt * AQ + wid * 16 + (lane >> 2) + half * 8;
            int col = h * HDD + nt * 8 + (lane & 3) * 2;
            size_t off = (size_t)(b * SS + row) * DD + col;
            float v0 = o[nt][half*2 + 0] * inv[half];
            float v1 = o[nt][half*2 + 1] * inv[half];
            uint32_t hp = pack_bf16(v0, v1);
            *(uint32_t*)&ohi[off] = hp;
            __nv_bfloat16* hb = (__nv_bfloat16*)&hp;
            *(uint32_t*)&olo[off] = pack_bf16(v0 - __bfloat162float(hb[0]),
                                              v1 - __bfloat162float(hb[1]));
        }
    }
}

// ---------------- RMSNorm + split ----------------
__global__ __launch_bounds__(256)
void rmsnorm_split_kernel(const float* __restrict__ x, const float* __restrict__ w,
                          __nv_bfloat16* __restrict__ ohi, __nv_bfloat16* __restrict__ olo)
{
    int row = blockIdx.x;
    const float* xr = x + (size_t)row * DD;
    int t = threadIdx.x;

    float v0 = xr[t], v1 = xr[t + 256], v2 = xr[t + 512], v3 = xr[t + 768];
    float ss = v0*v0 + v1*v1 + v2*v2 + v3*v3;
    #pragma unroll
    for (int off = 16; off; off >>= 1) ss += __shfl_xor_sync(0xffffffffu, ss, off);
    __shared__ float red[8];
    int wid = t >> 5, lid = t & 31;
    if (lid == 0) red[wid] = ss;
    __syncthreads();
    float tot = red[0]+red[1]+red[2]+red[3]+red[4]+red[5]+red[6]+red[7];
    float inv = rsqrtf(tot * (1.0f / (float)DD) + 1e-6f);

    size_t base = (size_t)row * DD;
    #pragma unroll
    for (int i = 0; i < 4; i++) {
        int c = t + i * 256;
        float val = w[c] * (i==0?v0:i==1?v1:i==2?v2:v3) * inv;
        __nv_bfloat16 hi = __float2bfloat16(val);
        ohi[base + c] = hi;
        olo[base + c] = __float2bfloat16(val - __bfloat162float(hi));
    }
}

// ---------------- weight transpose + split (separate launches, proven) ------
__global__ __launch_bounds__(256)
void tsplit_kernel(const float* __restrict__ src, __nv_bfloat16* __restrict__ dhi,
                   __nv_bfloat16* __restrict__ dlo, int Ks, int Ns, int Kout)
{
    __shared__ float ts[32][33];
    int kt = blockIdx.x * 32, nt = blockIdx.y * 32;
    int tx = threadIdx.x & 31, ty = threadIdx.x >> 5;
    #pragma unroll
    for (int i = 0; i < 4; i++) {
        int k = kt + ty + 8 * i, n = nt + tx;
        ts[ty + 8 * i][tx] = (k < Ks && n < Ns) ? src[(size_t)k * Ns + n] : 0.0f;
    }
    __syncthreads();
    #pragma unroll
    for (int i = 0; i < 4; i++) {
        int n = nt + ty + 8 * i, k = kt + tx;
        if (k >= Kout) continue;
        float v = ts[tx][ty + 8 * i];
        __nv_bfloat16 hi = __float2bfloat16(v);
        dhi[(size_t)n * Kout + k] = hi;
        dlo[(size_t)n * Kout + k] = __float2bfloat16(v - __bfloat162float(hi));
    }
}

__global__ __launch_bounds__(256)
void bias_concat_kernel(const float* __restrict__ bq, const float* __restrict__ bk,
                        const float* __restrict__ bv, float* __restrict__ dst)
{
    int i = blockIdx.x * 256 + threadIdx.x;
    if (i < 1024)       dst[i] = bq[i];
    else if (i < 2048)  dst[i] = bk[i - 1024];
    else if (i < 3072)  dst[i] = bv[i - 2048];
}

// ---------------- launch ----------------
extern "C" void kernel_launch(void* const* d_in, const int* in_sizes, int n_in,
                              void* d_out, int out_size)
{
    const float* x      = (const float*)d_in[0];
    const float* wq     = (const float*)d_in[1];
    const float* bq     = (const float*)d_in[2];
    const float* wk     = (const float*)d_in[3];
    const float* bk     = (const float*)d_in[4];
    const float* wv     = (const float*)d_in[5];
    const float* bv     = (const float*)d_in[6];
    const float* wo     = (const float*)d_in[7];
    const float* bo     = (const float*)d_in[8];
    const float* w_gate = (const float*)d_in[9];
    const float* w_up   = (const float*)d_in[10];
    const float* w_down = (const float*)d_in[11];
    const float* ln1w   = (const float*)d_in[12];
    const float* ln2w   = (const float*)d_in[13];
    const unsigned char* kpm = (const unsigned char*)d_in[16];
    float* out = (float*)d_out;

    __nv_bfloat16 *h_hi, *h_lo, *qkv_hi, *qkv_lo, *attn_hi, *attn_lo, *h2_hi, *h2_lo, *act_hi, *act_lo;
    __nv_bfloat16 *wqkvT_hi, *wqkvT_lo, *woT_hi, *woT_lo, *wguT_hi, *wguT_lo, *wdT_hi, *wdT_lo;
    float *res1, *bqkv;
    cudaGetSymbolAddress((void**)&h_hi, g_h_hi);     cudaGetSymbolAddress((void**)&h_lo, g_h_lo);
    cudaGetSymbolAddress((void**)&qkv_hi, g_qkv_hi); cudaGetSymbolAddress((void**)&qkv_lo, g_qkv_lo);
    cudaGetSymbolAddress((void**)&attn_hi, g_attn_hi); cudaGetSymbolAddress((void**)&attn_lo, g_attn_lo);
    cudaGetSymbolAddress((void**)&res1, g_res1);
    cudaGetSymbolAddress((void**)&h2_hi, g_h2_hi);   cudaGetSymbolAddress((void**)&h2_lo, g_h2_lo);
    cudaGetSymbolAddress((void**)&act_hi, g_act_hi); cudaGetSymbolAddress((void**)&act_lo, g_act_lo);
    cudaGetSymbolAddress((void**)&wqkvT_hi, g_wqkvT_hi); cudaGetSymbolAddress((void**)&wqkvT_lo, g_wqkvT_lo);
    cudaGetSymbolAddress((void**)&woT_hi, g_woT_hi); cudaGetSymbolAddress((void**)&woT_lo, g_woT_lo);
    cudaGetSymbolAddress((void**)&wguT_hi, g_wguT_hi); cudaGetSymbolAddress((void**)&wguT_lo, g_wguT_lo);
    cudaGetSymbolAddress((void**)&wdT_hi, g_wdT_hi); cudaGetSymbolAddress((void**)&wdT_lo, g_wdT_lo);
    cudaGetSymbolAddress((void**)&bqkv, g_bqkv);

    cudaFuncSetAttribute(tc_gemm, cudaFuncAttributeMaxDynamicSharedMemorySize, GEMM_SMEM);
    cudaFuncSetAttribute(tc_gemm_swiglu, cudaFuncAttributeMaxDynamicSharedMemorySize, MLP_SMEM);
    cudaFuncSetAttribute(attn_mma_kernel, cudaFuncAttributeMaxDynamicSharedMemorySize, ATTN_SMEM);

    // weight prep (separate launches — proven cheap; no dynamic struct indexing)
    tsplit_kernel<<<dim3(32, 32), 256>>>(wq, wqkvT_hi,               wqkvT_lo,               1024, 1024, 1024);
    tsplit_kernel<<<dim3(32, 32), 256>>>(wk, wqkvT_hi + 1024 * 1024, wqkvT_lo + 1024 * 1024, 1024, 1024, 1024);
    tsplit_kernel<<<dim3(32, 32), 256>>>(wv, wqkvT_hi + 2048 * 1024, wqkvT_lo + 2048 * 1024, 1024, 1024, 1024);
    tsplit_kernel<<<dim3(32, 32), 256>>>(wo, woT_hi, woT_lo, 1024, 1024, 1024);
    tsplit_kernel<<<dim3(32, 120), 256>>>(w_gate, wguT_hi,               wguT_lo,               1024, II, 1024);
    tsplit_kernel<<<dim3(32, 120), 256>>>(w_up,   wguT_hi + IPAD * 1024, wguT_lo + IPAD * 1024, 1024, II, 1024);
    tsplit_kernel<<<dim3(120, 32), 256>>>(w_down, wdT_hi, wdT_lo, II, 1024, IPAD);
    bias_concat_kernel<<<12, 256>>>(bq, bk, bv, bqkv);

    // 1) h = rmsnorm(x) -> hi/lo
    rmsnorm_split_kernel<<<MM, 256>>>(x, ln1w, h_hi, h_lo);
    // 2) qkv = h @ Wqkv^T + bqkv -> bf16 hi/lo (q pre-scaled by 0.125)
    tc_gemm<<<dim3(QKVN / 128, MM / 128), 256, GEMM_SMEM>>>(h_hi, h_lo, wqkvT_hi, wqkvT_lo,
        bqkv, nullptr, nullptr, DD, QKVN, qkv_hi, qkv_lo, 1024);
    // 3) attention (HMMA, heavy-first schedule)
    attn_mma_kernel<<<dim3(SS / AQ, BB * HH), 256, ATTN_SMEM>>>(qkv_hi, qkv_lo, kpm, attn_hi, attn_lo);
    // 4) res1 = attn @ Wo^T + bo + x
    tc_gemm<<<dim3(DD / 128, MM / 128), 256, GEMM_SMEM>>>(attn_hi, attn_lo, woT_hi, woT_lo,
        bo, x, res1, DD, DD, nullptr, nullptr, 0);
    // 5) h2 = rmsnorm(res1) -> hi/lo
    rmsnorm_split_kernel<<<MM, 256>>>(res1, ln2w, h2_hi, h2_lo);
    // 6+7) act = silu(h2@Wg^T) * (h2@Wu^T) -> bf16 hi/lo, fused
    tc_gemm_swiglu<<<dim3(IPAD / 128, MM / 128), 256, MLP_SMEM>>>(h2_hi, h2_lo,
        wguT_hi, wguT_lo, act_hi, act_lo);
    // 8) out = act @ Wdown^T + res1
    tc_gemm<<<dim3(DD / 128, MM / 128), 256, GEMM_SMEM>>>(act_hi, act_lo, wdT_hi, wdT_lo,
        nullptr, res1, out, IPAD, DD, nullptr, nullptr, 0);

    (void)in_sizes; (void)n_in; (void)out_size;
}